// round 14
// baseline (speedup 1.0000x reference)
#include <cuda_runtime.h>
#include <cuda_bf16.h>
#include <cstdint>

#define NC_MAX 1000000
#define NP_MAX 100000
#define DIM 64
#define H 4
#define DQK 8
#define DH 32
#define RPE 9
#define KVW 96
#define SCALE 0.35355339059327373f  // 8^-0.5

#if defined(__CUDA_ARCH_FEAT_SM103_ALL) || defined(__CUDA_ARCH_FEAT_SM100_ALL)
#define HAS_TCGEN05 1
#else
#define HAS_TCGEN05 0
#endif

// ---------------- smem helpers ----------------
__device__ __forceinline__ uint32_t smem_u32(const void* p) {
    uint32_t a;
    asm("{ .reg .u64 t; cvta.to.shared.u64 t, %1; cvt.u32.u64 %0, t; }"
        : "=r"(a) : "l"(p));
    return a;
}
#define SW128(b) ((b) ^ (((b) >> 3) & 0x70))

#if HAS_TCGEN05
__device__ __forceinline__ uint32_t elect1() {
    uint32_t p;
    asm volatile("{ .reg .pred p; elect.sync _|p, 0xFFFFFFFF; selp.b32 %0, 1, 0, p; }"
                 : "=r"(p));
    return p;
}
__device__ __forceinline__ uint64_t mk_desc(uint32_t addr) {
    return ((uint64_t)2 << 61) | ((uint64_t)1 << 46) | ((uint64_t)64 << 32)
         | ((uint64_t)1 << 16) | ((uint64_t)(addr >> 4) & 0x3FFF);
}
__device__ __forceinline__ float tf32_rna(float x) {
    uint32_t u;
    asm("cvt.rna.tf32.f32 %0, %1;" : "=r"(u) : "f"(x));
    return __uint_as_float(u);
}

#define TCGEN05_MMA_TF32_SS(dt, ad, bd, id, en) do {                           \
    uint32_t _en = (en) ? 1u : 0u;                                             \
    asm volatile("{\n\t.reg .pred p;\n\tsetp.ne.u32 p, %5, 0;\n\t"             \
        "tcgen05.mma.cta_group::1.kind::tf32 [%0], %1, %2, %3, {%4,%4,%4,%4}, p;\n\t}" \
        :: "r"(dt), "l"(ad), "l"(bd), "r"(id), "r"(0u), "r"(_en) : "memory");  \
} while (0)

#define LDTM32(r, addr)                                                        \
    asm volatile("tcgen05.ld.sync.aligned.32x32b.x32.b32 "                     \
        "{%0,%1,%2,%3,%4,%5,%6,%7,%8,%9,%10,%11,%12,%13,%14,%15,"              \
        "%16,%17,%18,%19,%20,%21,%22,%23,%24,%25,%26,%27,%28,%29,%30,%31}, [%32];" \
        : "=r"((r)[0]),"=r"((r)[1]),"=r"((r)[2]),"=r"((r)[3]),                 \
          "=r"((r)[4]),"=r"((r)[5]),"=r"((r)[6]),"=r"((r)[7]),                 \
          "=r"((r)[8]),"=r"((r)[9]),"=r"((r)[10]),"=r"((r)[11]),               \
          "=r"((r)[12]),"=r"((r)[13]),"=r"((r)[14]),"=r"((r)[15]),             \
          "=r"((r)[16]),"=r"((r)[17]),"=r"((r)[18]),"=r"((r)[19]),             \
          "=r"((r)[20]),"=r"((r)[21]),"=r"((r)[22]),"=r"((r)[23]),             \
          "=r"((r)[24]),"=r"((r)[25]),"=r"((r)[26]),"=r"((r)[27]),             \
          "=r"((r)[28]),"=r"((r)[29]),"=r"((r)[30]),"=r"((r)[31]) : "r"(addr))

#define MBAR_WAIT(mbar, ph) do {                                               \
    uint32_t _done;                                                            \
    asm volatile("{\n\t.reg .pred p;\n\t"                                      \
        "mbarrier.try_wait.parity.acquire.cta.shared::cta.b64 p, [%1], %2;\n\t"\
        "selp.b32 %0, 1, 0, p;\n\t}"                                           \
        : "=r"(_done) : "r"(mbar), "r"(ph) : "memory");                        \
    if (!_done) {                                                              \
        asm volatile("{\n\t.reg .pred P1;\n\t"                                 \
            "WL_%=:\n\t"                                                       \
            "mbarrier.try_wait.parity.acquire.cta.shared::cta.b64 P1, [%0], %1, 0x989680;\n\t" \
            "@P1 bra.uni WD_%=;\n\t"                                           \
            "bra.uni WL_%=;\n\t"                                               \
            "WD_%=:\n\t}"                                                      \
            :: "r"(mbar), "r"(ph) : "memory");                                 \
    }                                                                          \
} while (0)

#define IDESC_V ((1u << 4) | (2u << 7) | (2u << 10) | (8u << 17) | (8u << 24))
#define IDESC_C ((1u << 4) | (2u << 7) | (2u << 10) | (4u << 17) | (8u << 24))
#endif  // HAS_TCGEN05

// ---------------- device scratch ----------------
__device__ __align__(16) float g_qp[NP_MAX * DH];
__device__ __align__(16) float g_s[NP_MAX * H];
__device__ int g_idx[NC_MAX];
__device__ int g_is64;

// ---------------- index dtype detection ----------------
__global__ void detect_kernel(const unsigned int* __restrict__ raw, int nc) {
    __shared__ int found;
    if (threadIdx.x == 0) found = 0;
    __syncthreads();
    int limit = nc / 2; if (limit > 2048) limit = 2048;
    for (int i = threadIdx.x; i < limit; i += blockDim.x)
        if (raw[2 * i + 1] != 0u) found = 1;
    __syncthreads();
    if (threadIdx.x == 0) g_is64 = (found == 0) ? 1 : 0;
}

__global__ void cvt_index_kernel(const void* __restrict__ idxp, int nc) {
    int i = blockIdx.x * blockDim.x + threadIdx.x;
    if (i >= nc) return;
    if (g_is64) g_idx[i] = (int)((const long long*)idxp)[i];
    else        g_idx[i] = ((const int*)idxp)[i];
}

// ---------------- parent query projection ----------------
__global__ void __launch_bounds__(256, 2) qp_kernel(
    const float* __restrict__ x_parent, const float* __restrict__ wq,
    const float* __restrict__ bq, int np)
{
    const int t = threadIdx.x & 31;
    const int w = threadIdx.x >> 5;
    __shared__ __align__(16) float xs[8][64];

    float wr[64];
#pragma unroll
    for (int c = 0; c < 64; c++) wr[c] = wq[c * DH + t];
    const float b = bq[t];

    const int warps_total = gridDim.x * 8;
    for (int p = blockIdx.x * 8 + w; p < np; p += warps_total) {
        size_t base = (size_t)p * DIM;
        xs[w][t]      = x_parent[base + t];
        xs[w][t + 32] = x_parent[base + 32 + t];
        __syncwarp();
        float a0 = b, a1 = 0.f, a2 = 0.f, a3 = 0.f;
#pragma unroll
        for (int c = 0; c < 64; c += 4) {
            float4 xv = *(const float4*)&xs[w][c];
            a0 += xv.x * wr[c];
            a1 += xv.y * wr[c + 1];
            a2 += xv.z * wr[c + 2];
            a3 += xv.w * wr[c + 3];
        }
        g_qp[(size_t)p * DH + t] = ((a0 + a1) + (a2 + a3)) * SCALE;
        __syncwarp();
    }
}

// ======================= fused, depth-2 pipelined =======================
// Tile M=128 children, 128 threads. Double-buffered A (hi+lo), two TMEM D
// regions (cols 0-95 / 128-223), two mbarriers. Per iteration: stage A(t+1)
// into the other buffer, issue its MMAs, prefetch tile-t gathers, THEN wait
// tile-t's mbar -> LDTM -> epilogue. Loads are in flight during every wait.
#define AH_BYTES (128 * 64 * 4)   // 32768
#define ABUF_BYTES (2 * AH_BYTES) // hi+lo per buffer
#define BK_BYTES (32 * 64 * 4)    // 8192
#define BV_BYTES (64 * 64 * 4)    // 16384
#define FDYN_BYTES (2 * ABUF_BYTES + BK_BYTES + 2 * BV_BYTES + 1024)  // 173056

__device__ __forceinline__ uint32_t a_off(int child, int col) {
    return SW128((uint32_t)(((child >> 3) + ((col >= 32) ? 16 : 0)) * 1024
                 + (child & 7) * 128 + (col & 31) * 4));
}
__device__ __forceinline__ uint32_t bk_off(int n, int k) {
    return SW128((uint32_t)(((n >> 3) + (k >> 5) * 4) * 1024
                 + (n & 7) * 128 + (k & 31) * 4));
}
__device__ __forceinline__ uint32_t bv_off(int n, int k) {
    return SW128((uint32_t)(((n >> 3) + (k >> 5) * 8) * 1024
                 + (n & 7) * 128 + (k & 31) * 4));
}

__global__ void __launch_bounds__(128) fused_kernel(
    const float* __restrict__ x_child, const float* __restrict__ edge_attr,
    const float* __restrict__ wkv, const float* __restrict__ bkv,
    const float* __restrict__ wk_rpe, const float* __restrict__ bk_rpe,
    const float* __restrict__ wq_rpe, const float* __restrict__ bq_rpe,
    float* __restrict__ out, int nc, int ntiles)
{
#if HAS_TCGEN05
    extern __shared__ __align__(16) char fdyn[];
    __shared__ __align__(16) float wkr_s[RPE][32];
    __shared__ __align__(16) float wqr_s[RPE][32];
    __shared__ __align__(16) float bkc[32];
    __shared__ __align__(16) float bqr[32];
    __shared__ __align__(16) float bv_s[64];
    __shared__ __align__(8) unsigned long long mbar_store[2];
    __shared__ uint32_t tmem_ptr_store;

    const int tid = threadIdx.x;
    const int wid = tid >> 5;

    uint32_t base_u = smem_u32(fdyn);
    uint32_t pad = (1024u - (base_u & 1023u)) & 1023u;
    char* A0  = fdyn + pad;              // buf0: hi | lo
    char* A1  = A0 + ABUF_BYTES;         // buf1: hi | lo
    char* Bk  = A1 + ABUF_BYTES;
    char* Bvh = Bk + BK_BYTES;
    char* Bvl = Bvh + BV_BYTES;
    const uint32_t a0_base  = base_u + pad;
    const uint32_t a1_base  = a0_base + ABUF_BYTES;
    const uint32_t bk_base  = a1_base + ABUF_BYTES;
    const uint32_t bvh_base = bk_base + BK_BYTES;
    const uint32_t bvl_base = bvh_base + BV_BYTES;
    const uint32_t mbar0 = smem_u32(&mbar_store[0]);
    const uint32_t mbar1 = smem_u32(&mbar_store[1]);

    if (wid == 0) {
        asm volatile("tcgen05.alloc.cta_group::1.sync.aligned.shared::cta.b32 [%0], %1;"
                     :: "r"(smem_u32(&tmem_ptr_store)), "r"(256u) : "memory");
        asm volatile("tcgen05.relinquish_alloc_permit.cta_group::1.sync.aligned;");
    }
    if (tid == 0) {
        asm volatile("mbarrier.init.shared.b64 [%0], %1;" :: "r"(mbar0), "r"(1u) : "memory");
        asm volatile("mbarrier.init.shared.b64 [%0], %1;" :: "r"(mbar1), "r"(1u) : "memory");
    }

    // one-time weight staging
    for (int idx = tid; idx < 32 * 64; idx += 128) {
        int n = idx >> 6, k = idx & 63;
        *(float*)(Bk + bk_off(n, k)) = wkv[k * KVW + n];
    }
    for (int idx = tid; idx < 64 * 64; idx += 128) {
        int n = idx >> 6, k = idx & 63;
        float w = wkv[k * KVW + DH + n];
        float hi = tf32_rna(w);
        *(float*)(Bvh + bv_off(n, k)) = hi;
        *(float*)(Bvl + bv_off(n, k)) = w - hi;
    }
    for (int idx = tid; idx < RPE * 32; idx += 128) {
        wkr_s[0][idx] = wk_rpe[idx];
        wqr_s[0][idx] = wq_rpe[idx];
    }
    if (tid < 32) {
        bkc[tid] = bkv[tid] + bk_rpe[tid];
        bqr[tid] = bq_rpe[tid];
    }
    if (tid < 64) bv_s[tid] = bkv[DH + tid];
    __syncthreads();

    const uint32_t tmem = tmem_ptr_store;
    const uint64_t bk_d  = mk_desc(bk_base);
    const uint64_t bvh_d = mk_desc(bvh_base);
    const uint64_t bvl_d = mk_desc(bvl_base);
    uint32_t ph0 = 0, ph1 = 0;

    // ---- staging + MMA-issue macros ----
#define STAGE_A(t_, Abuf_) do {                                                \
    const int _i0 = (t_) * 128;                                                \
    char* _Ah = (Abuf_);                                                       \
    char* _Al = (Abuf_) + AH_BYTES;                                            \
    _Pragma("unroll")                                                          \
    for (int _k = 0; _k < 16; _k++) {                                          \
        int _idx = tid + 128 * _k;                                             \
        int _ch = _idx >> 4, _c4 = _idx & 15;                                  \
        int _i2 = _i0 + _ch;                                                   \
        float4 _xv = make_float4(0.f, 0.f, 0.f, 0.f);                          \
        if (_i2 < nc) _xv = *(const float4*)&x_child[(size_t)_i2 * DIM + _c4 * 4]; \
        float4 _hi, _lo;                                                       \
        _hi.x = tf32_rna(_xv.x); _lo.x = _xv.x - _hi.x;                        \
        _hi.y = tf32_rna(_xv.y); _lo.y = _xv.y - _hi.y;                        \
        _hi.z = tf32_rna(_xv.z); _lo.z = _xv.z - _hi.z;                        \
        _hi.w = tf32_rna(_xv.w); _lo.w = _xv.w - _hi.w;                        \
        uint32_t _off = a_off(_ch, _c4 * 4);                                   \
        *(float4*)(_Ah + _off) = _hi;                                          \
        *(float4*)(_Al + _off) = _lo;                                          \
    }                                                                          \
    asm volatile("fence.proxy.async.shared::cta;" ::: "memory");               \
} while (0)

#define ISSUE_MMA(abase_, dt_, mb_) do {                                       \
    const uint64_t _ah_d = mk_desc(abase_);                                    \
    const uint64_t _al_d = mk_desc((abase_) + AH_BYTES);                       \
    asm volatile("tcgen05.fence::after_thread_sync;" ::: "memory");            \
    if (elect1()) {                                                            \
        _Pragma("unroll")                                                      \
        for (int _s = 0; _s < 8; _s++) {                                       \
            uint64_t _ao = (uint64_t)((_s >> 2) * 1024 + (_s & 3) * 2);        \
            uint64_t _bo = (uint64_t)((_s >> 2) * 256 + (_s & 3) * 2);         \
            TCGEN05_MMA_TF32_SS((dt_), _ah_d + _ao, bk_d + _bo, IDESC_C, _s > 0); \
        }                                                                      \
        _Pragma("unroll")                                                      \
        for (int _pass = 0; _pass < 3; _pass++) {                              \
            uint64_t _ad = (_pass == 1) ? _al_d : _ah_d;                       \
            uint64_t _bd = (_pass == 2) ? bvl_d : bvh_d;                       \
            _Pragma("unroll")                                                  \
            for (int _s = 0; _s < 8; _s++) {                                   \
                uint64_t _ao = (uint64_t)((_s >> 2) * 1024 + (_s & 3) * 2);    \
                uint64_t _bo = (uint64_t)((_s >> 2) * 512 + (_s & 3) * 2);     \
                TCGEN05_MMA_TF32_SS((dt_) + 32, _ad + _ao, _bd + _bo, IDESC_V, \
                                    !(_pass == 0 && _s == 0));                 \
            }                                                                  \
        }                                                                      \
        asm volatile(                                                          \
            "tcgen05.commit.cta_group::1.mbarrier::arrive::one.shared::cluster.b64 [%0];" \
            :: "r"(mb_) : "memory");                                           \
    }                                                                          \
} while (0)

    int t = blockIdx.x;
    int slot = 0;
    if (t < ntiles) {
        // prologue: stage + issue tile t into slot 0
        STAGE_A(t, A0);
        __syncthreads();
        if (wid == 0) ISSUE_MMA(a0_base, tmem, mbar0);
    }

    while (t < ntiles) {
        const int tn = t + gridDim.x;
        const int nslot = 1 - slot;

        // stage + issue the NEXT tile into the other buffer/D-region
        if (tn < ntiles) {
            STAGE_A(tn, nslot ? A1 : A0);
            __syncthreads();
            if (wid == 0) ISSUE_MMA(nslot ? a1_base : a0_base,
                                    tmem + nslot * 128, nslot ? mbar1 : mbar0);
        }

        // prefetch this tile's gathers while its MMA (and next's) are in flight
        const int i = t * 128 + tid;
        const bool live = (i < nc);
        const int p = live ? g_idx[i] : 0;
        float ea[RPE];
#pragma unroll
        for (int r = 0; r < RPE; r++)
            ea[r] = live ? edge_attr[(size_t)i * RPE + r] : 0.f;
        float qpr[32];
        {
            const float4* qv = (const float4*)&g_qp[(size_t)p * DH];
#pragma unroll
            for (int u = 0; u < 8; u++) {
                float4 v = live ? qv[u] : make_float4(0.f, 0.f, 0.f, 0.f);
                qpr[u * 4 + 0] = v.x; qpr[u * 4 + 1] = v.y;
                qpr[u * 4 + 2] = v.z; qpr[u * 4 + 3] = v.w;
            }
        }

        // wait for THIS tile's MMA
        if (slot) { MBAR_WAIT(mbar1, ph1); ph1 ^= 1; }
        else      { MBAR_WAIT(mbar0, ph0); ph0 ^= 1; }
        asm volatile("tcgen05.fence::after_thread_sync;" ::: "memory");

        uint32_t dk[32], dv[64];
        const uint32_t dbase = tmem + slot * 128;
        LDTM32(dk, dbase);
        LDTM32(dv, dbase + 32);
        LDTM32(dv + 32, dbase + 64);
        asm volatile("tcgen05.wait::ld.sync.aligned;" ::: "memory");

        if (live) {
            float e4[4];
#pragma unroll
            for (int h = 0; h < 4; h++) {
                float c = 0.f;
#pragma unroll
                for (int j = 0; j < 8; j++) {
                    int col = h * 8 + j;
                    float kv = __uint_as_float(dk[col]) + bkc[col];
                    float qv = qpr[col] + bqr[col];
#pragma unroll
                    for (int r = 0; r < RPE; r++) {
                        kv += ea[r] * wkr_s[r][col];
                        qv += ea[r] * wqr_s[r][col];
                    }
                    c += qv * kv;
                }
                e4[h] = __expf(c);
            }
            asm volatile("red.global.add.v4.f32 [%0], {%1,%2,%3,%4};"
                         :: "l"(g_s + (size_t)p * H),
                            "f"(e4[0]), "f"(e4[1]), "f"(e4[2]), "f"(e4[3]) : "memory");

            float* dst = out + (size_t)p * DIM;
#pragma unroll
            for (int g = 0; g < 16; g++) {
                int col = g * 4;
                float e = e4[g >> 2];
                float r0 = (__uint_as_float(dv[col + 0]) + bv_s[col + 0]) * e;
                float r1 = (__uint_as_float(dv[col + 1]) + bv_s[col + 1]) * e;
                float r2 = (__uint_as_float(dv[col + 2]) + bv_s[col + 2]) * e;
                float r3 = (__uint_as_float(dv[col + 3]) + bv_s[col + 3]) * e;
                asm volatile("red.global.add.v4.f32 [%0], {%1,%2,%3,%4};"
                             :: "l"(dst + col), "f"(r0), "f"(r1), "f"(r2), "f"(r3)
                             : "memory");
            }
        }
        asm volatile("tcgen05.fence::before_thread_sync;" ::: "memory");
        __syncthreads();   // D[slot] consumed; buf[slot] free for restage

        t = tn;
        slot = nslot;
    }

    __syncthreads();
    if (tid == 0) {
        asm volatile("mbarrier.inval.shared.b64 [%0];" :: "r"(mbar0) : "memory");
        asm volatile("mbarrier.inval.shared.b64 [%0];" :: "r"(mbar1) : "memory");
    }
    __syncthreads();
    if (wid == 0)
        asm volatile("tcgen05.dealloc.cta_group::1.sync.aligned.b32 %0, %1;"
                     :: "r"(tmem), "r"(256u));
#else
    // fallback for the plain compute_103 PTX pass (never executes on the GPU)
    const int tid = threadIdx.x;
    for (int tile = blockIdx.x; tile < ntiles; tile += gridDim.x) {
        int i = tile * 128 + tid;
        if (i < nc) {
            int p = g_idx[i];
            float ea[RPE];
            for (int r = 0; r < RPE; r++) ea[r] = edge_attr[(size_t)i * RPE + r];
            float e4[4];
            for (int h = 0; h < 4; h++) {
                float c = 0.f;
                for (int j = 0; j < 8; j++) {
                    int col = h * 8 + j;
                    float kv = bkv[col] + bk_rpe[col];
                    for (int cd = 0; cd < 64; cd++)
                        kv += x_child[(size_t)i * DIM + cd] * wkv[cd * KVW + col];
                    float qv = g_qp[(size_t)p * DH + col] + bq_rpe[col];
                    for (int r = 0; r < RPE; r++) {
                        kv += ea[r] * wk_rpe[r * DH + col];
                        qv += ea[r] * wq_rpe[r * DH + col];
                    }
                    c += qv * kv;
                }
                e4[h] = __expf(c);
            }
            for (int h = 0; h < 4; h++) atomicAdd(g_s + (size_t)p * H + h, e4[h]);
            for (int j = 0; j < 64; j++) {
                float a = bkv[DH + j];
                for (int cd = 0; cd < 64; cd++)
                    a += x_child[(size_t)i * DIM + cd] * wkv[cd * KVW + DH + j];
                atomicAdd(out + (size_t)p * DIM + j, a * e4[j >> 4]);
            }
        }
    }
#endif
}

// ---------------- final normalize ----------------
__global__ void norm_kernel(float* __restrict__ out, int np) {
    int idx = blockIdx.x * blockDim.x + threadIdx.x;
    if (idx >= np * 16) return;
    int p = idx >> 4, grp = idx & 15;
    float s = g_s[p * H + (grp >> 2)];
    float inv = 1.0f / (s + 1e-16f);
    float4 v = *(const float4*)&out[(size_t)p * DIM + grp * 4];
    v.x *= inv; v.y *= inv; v.z *= inv; v.w *= inv;
    *(float4*)&out[(size_t)p * DIM + grp * 4] = v;
}

// ---------------- launch ----------------
extern "C" void kernel_launch(void* const* d_in, const int* in_sizes, int n_in,
                              void* d_out, int out_size) {
    const float* x_child   = (const float*)d_in[0];
    const float* x_parent  = (const float*)d_in[1];
    const void*  index     = d_in[2];
    const float* edge_attr = (const float*)d_in[3];
    const float* wq        = (const float*)d_in[4];
    const float* bq        = (const float*)d_in[5];
    const float* wkv       = (const float*)d_in[6];
    const float* bkv       = (const float*)d_in[7];
    const float* wk_rpe    = (const float*)d_in[8];
    const float* bk_rpe    = (const float*)d_in[9];
    const float* wq_rpe    = (const float*)d_in[10];
    const float* bq_rpe    = (const float*)d_in[11];
    float* out = (float*)d_out;

    const int nc = in_sizes[0] / DIM;
    const int np = in_sizes[1] / DIM;

    static int attr_done = 0;
    if (!attr_done) {
        cudaFuncSetAttribute(fused_kernel,
                             cudaFuncAttributeMaxDynamicSharedMemorySize, FDYN_BYTES);
        attr_done = 1;
    }

    cudaMemsetAsync(d_out, 0, (size_t)out_size * sizeof(float));
    void* s_addr = nullptr;
    cudaGetSymbolAddress(&s_addr, g_s);
    cudaMemsetAsync(s_addr, 0, (size_t)np * H * sizeof(float));

    detect_kernel<<<1, 256>>>((const unsigned int*)index, nc);
    cvt_index_kernel<<<(nc + 255) / 256, 256>>>(index, nc);

    qp_kernel<<<208, 256>>>(x_parent, wq, bq, np);

    const int ntiles = (nc + 127) / 128;
    fused_kernel<<<148, 128, FDYN_BYTES>>>(x_child, edge_attr, wkv, bkv,
                                           wk_rpe, bk_rpe, wq_rpe, bq_rpe,
                                           out, nc, ntiles);

    norm_kernel<<<(np * 16 + 255) / 256, 256>>>(out, np);
}

// round 15
// speedup vs baseline: 1.0408x; 1.0408x over previous
#include <cuda_runtime.h>
#include <cuda_bf16.h>
#include <cstdint>

#define NC_MAX 1000000
#define NP_MAX 100000
#define DIM 64
#define H 4
#define DQK 8
#define DH 32
#define RPE 9
#define KVW 96
#define SCALE 0.35355339059327373f  // 8^-0.5

#if defined(__CUDA_ARCH_FEAT_SM103_ALL) || defined(__CUDA_ARCH_FEAT_SM100_ALL)
#define HAS_TCGEN05 1
#else
#define HAS_TCGEN05 0
#endif

// ---------------- smem helpers ----------------
__device__ __forceinline__ uint32_t smem_u32(const void* p) {
    uint32_t a;
    asm("{ .reg .u64 t; cvta.to.shared.u64 t, %1; cvt.u32.u64 %0, t; }"
        : "=r"(a) : "l"(p));
    return a;
}
#define SW128(b) ((b) ^ (((b) >> 3) & 0x70))

#if HAS_TCGEN05
__device__ __forceinline__ uint32_t elect1() {
    uint32_t p;
    asm volatile("{ .reg .pred p; elect.sync _|p, 0xFFFFFFFF; selp.b32 %0, 1, 0, p; }"
                 : "=r"(p));
    return p;
}
__device__ __forceinline__ uint64_t mk_desc(uint32_t addr) {
    return ((uint64_t)2 << 61) | ((uint64_t)1 << 46) | ((uint64_t)64 << 32)
         | ((uint64_t)1 << 16) | ((uint64_t)(addr >> 4) & 0x3FFF);
}
__device__ __forceinline__ float tf32_rna(float x) {
    uint32_t u;
    asm("cvt.rna.tf32.f32 %0, %1;" : "=r"(u) : "f"(x));
    return __uint_as_float(u);
}

#define TCGEN05_MMA_TF32_SS(dt, ad, bd, id, en) do {                           \
    uint32_t _en = (en) ? 1u : 0u;                                             \
    asm volatile("{\n\t.reg .pred p;\n\tsetp.ne.u32 p, %5, 0;\n\t"             \
        "tcgen05.mma.cta_group::1.kind::tf32 [%0], %1, %2, %3, {%4,%4,%4,%4}, p;\n\t}" \
        :: "r"(dt), "l"(ad), "l"(bd), "r"(id), "r"(0u), "r"(_en) : "memory");  \
} while (0)

#define LDTM32(r, addr)                                                        \
    asm volatile("tcgen05.ld.sync.aligned.32x32b.x32.b32 "                     \
        "{%0,%1,%2,%3,%4,%5,%6,%7,%8,%9,%10,%11,%12,%13,%14,%15,"              \
        "%16,%17,%18,%19,%20,%21,%22,%23,%24,%25,%26,%27,%28,%29,%30,%31}, [%32];" \
        : "=r"((r)[0]),"=r"((r)[1]),"=r"((r)[2]),"=r"((r)[3]),                 \
          "=r"((r)[4]),"=r"((r)[5]),"=r"((r)[6]),"=r"((r)[7]),                 \
          "=r"((r)[8]),"=r"((r)[9]),"=r"((r)[10]),"=r"((r)[11]),               \
          "=r"((r)[12]),"=r"((r)[13]),"=r"((r)[14]),"=r"((r)[15]),             \
          "=r"((r)[16]),"=r"((r)[17]),"=r"((r)[18]),"=r"((r)[19]),             \
          "=r"((r)[20]),"=r"((r)[21]),"=r"((r)[22]),"=r"((r)[23]),             \
          "=r"((r)[24]),"=r"((r)[25]),"=r"((r)[26]),"=r"((r)[27]),             \
          "=r"((r)[28]),"=r"((r)[29]),"=r"((r)[30]),"=r"((r)[31]) : "r"(addr))

#define MBAR_WAIT(mbar, ph) do {                                               \
    uint32_t _done;                                                            \
    asm volatile("{\n\t.reg .pred p;\n\t"                                      \
        "mbarrier.try_wait.parity.acquire.cta.shared::cta.b64 p, [%1], %2;\n\t"\
        "selp.b32 %0, 1, 0, p;\n\t}"                                           \
        : "=r"(_done) : "r"(mbar), "r"(ph) : "memory");                        \
    if (!_done) {                                                              \
        asm volatile("{\n\t.reg .pred P1;\n\t"                                 \
            "WL_%=:\n\t"                                                       \
            "mbarrier.try_wait.parity.acquire.cta.shared::cta.b64 P1, [%0], %1, 0x989680;\n\t" \
            "@P1 bra.uni WD_%=;\n\t"                                           \
            "bra.uni WL_%=;\n\t"                                               \
            "WD_%=:\n\t}"                                                      \
            :: "r"(mbar), "r"(ph) : "memory");                                 \
    }                                                                          \
} while (0)

#define IDESC_V ((1u << 4) | (2u << 7) | (2u << 10) | (8u << 17) | (8u << 24))
#define IDESC_C ((1u << 4) | (2u << 7) | (2u << 10) | (4u << 17) | (8u << 24))
#endif  // HAS_TCGEN05

// ---------------- device scratch ----------------
__device__ __align__(16) float g_qp[NP_MAX * DH];
__device__ __align__(16) float g_s[NP_MAX * H];
__device__ int g_idx[NC_MAX];
__device__ int g_is64;

// ---------------- index dtype detection ----------------
__global__ void detect_kernel(const unsigned int* __restrict__ raw, int nc) {
    __shared__ int found;
    if (threadIdx.x == 0) found = 0;
    __syncthreads();
    int limit = nc / 2; if (limit > 2048) limit = 2048;
    for (int i = threadIdx.x; i < limit; i += blockDim.x)
        if (raw[2 * i + 1] != 0u) found = 1;
    __syncthreads();
    if (threadIdx.x == 0) g_is64 = (found == 0) ? 1 : 0;
}

__global__ void cvt_index_kernel(const void* __restrict__ idxp, int nc) {
    int i = blockIdx.x * blockDim.x + threadIdx.x;
    if (i >= nc) return;
    if (g_is64) g_idx[i] = (int)((const long long*)idxp)[i];
    else        g_idx[i] = ((const int*)idxp)[i];
}

// ---------------- parent query projection ----------------
__global__ void __launch_bounds__(256, 2) qp_kernel(
    const float* __restrict__ x_parent, const float* __restrict__ wq,
    const float* __restrict__ bq, int np)
{
    const int t = threadIdx.x & 31;
    const int w = threadIdx.x >> 5;
    __shared__ __align__(16) float xs[8][64];

    float wr[64];
#pragma unroll
    for (int c = 0; c < 64; c++) wr[c] = wq[c * DH + t];
    const float b = bq[t];

    const int warps_total = gridDim.x * 8;
    for (int p = blockIdx.x * 8 + w; p < np; p += warps_total) {
        size_t base = (size_t)p * DIM;
        xs[w][t]      = x_parent[base + t];
        xs[w][t + 32] = x_parent[base + 32 + t];
        __syncwarp();
        float a0 = b, a1 = 0.f, a2 = 0.f, a3 = 0.f;
#pragma unroll
        for (int c = 0; c < 64; c += 4) {
            float4 xv = *(const float4*)&xs[w][c];
            a0 += xv.x * wr[c];
            a1 += xv.y * wr[c + 1];
            a2 += xv.z * wr[c + 2];
            a3 += xv.w * wr[c + 3];
        }
        g_qp[(size_t)p * DH + t] = ((a0 + a1) + (a2 + a3)) * SCALE;
        __syncwarp();
    }
}

// ======================= fused, depth-2 pipelined, 256 threads =======================
// Tile M=128 children, 256 threads (8 warps). Double-buffered A (hi+lo), two
// TMEM D regions (cols 0-95 / 128-223), two mbarriers. Per iteration: stage
// A(t+1) into the other buffer + issue its MMAs, prefetch tile-t gathers,
// wait tile-t mbar, then split epilogue: warps 0-3 own e-compute + v cols
// 0-31, warps 4-7 own v cols 32-63 (e via shared broadcast).
#define AH_BYTES (128 * 64 * 4)   // 32768
#define ABUF_BYTES (2 * AH_BYTES) // hi+lo per buffer
#define BK_BYTES (32 * 64 * 4)    // 8192
#define BV_BYTES (64 * 64 * 4)    // 16384
#define FDYN_BYTES (2 * ABUF_BYTES + BK_BYTES + 2 * BV_BYTES + 1024)  // 173056

__device__ __forceinline__ uint32_t a_off(int child, int col) {
    return SW128((uint32_t)(((child >> 3) + ((col >= 32) ? 16 : 0)) * 1024
                 + (child & 7) * 128 + (col & 31) * 4));
}
__device__ __forceinline__ uint32_t bk_off(int n, int k) {
    return SW128((uint32_t)(((n >> 3) + (k >> 5) * 4) * 1024
                 + (n & 7) * 128 + (k & 31) * 4));
}
__device__ __forceinline__ uint32_t bv_off(int n, int k) {
    return SW128((uint32_t)(((n >> 3) + (k >> 5) * 8) * 1024
                 + (n & 7) * 128 + (k & 31) * 4));
}

__global__ void __launch_bounds__(256) fused_kernel(
    const float* __restrict__ x_child, const float* __restrict__ edge_attr,
    const float* __restrict__ wkv, const float* __restrict__ bkv,
    const float* __restrict__ wk_rpe, const float* __restrict__ bk_rpe,
    const float* __restrict__ wq_rpe, const float* __restrict__ bq_rpe,
    float* __restrict__ out, int nc, int ntiles)
{
#if HAS_TCGEN05
    extern __shared__ __align__(16) char fdyn[];
    __shared__ __align__(16) float wkr_s[RPE][32];
    __shared__ __align__(16) float wqr_s[RPE][32];
    __shared__ __align__(16) float bkc[32];
    __shared__ __align__(16) float bqr[32];
    __shared__ __align__(16) float bv_s[64];
    __shared__ __align__(16) float e_s[128][4];
    __shared__ __align__(8) unsigned long long mbar_store[2];
    __shared__ uint32_t tmem_ptr_store;

    const int tid = threadIdx.x;
    const int wid = tid >> 5;
    const int child = tid & 127;
    const int half = tid >> 7;          // 0: warps 0-3, 1: warps 4-7

    uint32_t base_u = smem_u32(fdyn);
    uint32_t pad = (1024u - (base_u & 1023u)) & 1023u;
    char* A0  = fdyn + pad;
    char* A1  = A0 + ABUF_BYTES;
    char* Bk  = A1 + ABUF_BYTES;
    char* Bvh = Bk + BK_BYTES;
    char* Bvl = Bvh + BV_BYTES;
    const uint32_t a0_base  = base_u + pad;
    const uint32_t a1_base  = a0_base + ABUF_BYTES;
    const uint32_t bk_base  = a1_base + ABUF_BYTES;
    const uint32_t bvh_base = bk_base + BK_BYTES;
    const uint32_t bvl_base = bvh_base + BV_BYTES;
    const uint32_t mbar0 = smem_u32(&mbar_store[0]);
    const uint32_t mbar1 = smem_u32(&mbar_store[1]);

    if (wid == 0) {
        asm volatile("tcgen05.alloc.cta_group::1.sync.aligned.shared::cta.b32 [%0], %1;"
                     :: "r"(smem_u32(&tmem_ptr_store)), "r"(256u) : "memory");
        asm volatile("tcgen05.relinquish_alloc_permit.cta_group::1.sync.aligned;");
    }
    if (tid == 0) {
        asm volatile("mbarrier.init.shared.b64 [%0], %1;" :: "r"(mbar0), "r"(1u) : "memory");
        asm volatile("mbarrier.init.shared.b64 [%0], %1;" :: "r"(mbar1), "r"(1u) : "memory");
    }

    // one-time weight staging
    for (int idx = tid; idx < 32 * 64; idx += 256) {
        int n = idx >> 6, k = idx & 63;
        *(float*)(Bk + bk_off(n, k)) = wkv[k * KVW + n];
    }
    for (int idx = tid; idx < 64 * 64; idx += 256) {
        int n = idx >> 6, k = idx & 63;
        float w = wkv[k * KVW + DH + n];
        float hi = tf32_rna(w);
        *(float*)(Bvh + bv_off(n, k)) = hi;
        *(float*)(Bvl + bv_off(n, k)) = w - hi;
    }
    for (int idx = tid; idx < RPE * 32; idx += 256) {
        wkr_s[0][idx] = wk_rpe[idx];
        wqr_s[0][idx] = wq_rpe[idx];
    }
    if (tid < 32) {
        bkc[tid] = bkv[tid] + bk_rpe[tid];
        bqr[tid] = bq_rpe[tid];
    }
    if (tid < 64) bv_s[tid] = bkv[DH + tid];
    __syncthreads();

    const uint32_t tmem = tmem_ptr_store;
    const uint64_t bk_d  = mk_desc(bk_base);
    const uint64_t bvh_d = mk_desc(bvh_base);
    const uint64_t bvl_d = mk_desc(bvl_base);
    uint32_t ph0 = 0, ph1 = 0;

#define STAGE_A(t_, Abuf_) do {                                                \
    const int _i0 = (t_) * 128;                                                \
    char* _Ah = (Abuf_);                                                       \
    char* _Al = (Abuf_) + AH_BYTES;                                            \
    _Pragma("unroll")                                                          \
    for (int _k = 0; _k < 8; _k++) {                                           \
        int _idx = tid + 256 * _k;                                             \
        int _ch = _idx >> 4, _c4 = _idx & 15;                                  \
        int _i2 = _i0 + _ch;                                                   \
        float4 _xv = make_float4(0.f, 0.f, 0.f, 0.f);                          \
        if (_i2 < nc) _xv = *(const float4*)&x_child[(size_t)_i2 * DIM + _c4 * 4]; \
        float4 _hi, _lo;                                                       \
        _hi.x = tf32_rna(_xv.x); _lo.x = _xv.x - _hi.x;                        \
        _hi.y = tf32_rna(_xv.y); _lo.y = _xv.y - _hi.y;                        \
        _hi.z = tf32_rna(_xv.z); _lo.z = _xv.z - _hi.z;                        \
        _hi.w = tf32_rna(_xv.w); _lo.w = _xv.w - _hi.w;                        \
        uint32_t _off = a_off(_ch, _c4 * 4);                                   \
        *(float4*)(_Ah + _off) = _hi;                                          \
        *(float4*)(_Al + _off) = _lo;                                          \
    }                                                                          \
    asm volatile("fence.proxy.async.shared::cta;" ::: "memory");               \
} while (0)

#define ISSUE_MMA(abase_, dt_, mb_) do {                                       \
    const uint64_t _ah_d = mk_desc(abase_);                                    \
    const uint64_t _al_d = mk_desc((abase_) + AH_BYTES);                       \
    asm volatile("tcgen05.fence::after_thread_sync;" ::: "memory");            \
    if (elect1()) {                                                            \
        _Pragma("unroll")                                                      \
        for (int _s = 0; _s < 8; _s++) {                                       \
            uint64_t _ao = (uint64_t)((_s >> 2) * 1024 + (_s & 3) * 2);        \
            uint64_t _bo = (uint64_t)((_s >> 2) * 256 + (_s & 3) * 2);         \
            TCGEN05_MMA_TF32_SS((dt_), _ah_d + _ao, bk_d + _bo, IDESC_C, _s > 0); \
        }                                                                      \
        _Pragma("unroll")                                                      \
        for (int _pass = 0; _pass < 3; _pass++) {                              \
            uint64_t _ad = (_pass == 1) ? _al_d : _ah_d;                       \
            uint64_t _bd = (_pass == 2) ? bvl_d : bvh_d;                       \
            _Pragma("unroll")                                                  \
            for (int _s = 0; _s < 8; _s++) {                                   \
                uint64_t _ao = (uint64_t)((_s >> 2) * 1024 + (_s & 3) * 2);    \
                uint64_t _bo = (uint64_t)((_s >> 2) * 512 + (_s & 3) * 2);     \
                TCGEN05_MMA_TF32_SS((dt_) + 32, _ad + _ao, _bd + _bo, IDESC_V, \
                                    !(_pass == 0 && _s == 0));                 \
            }                                                                  \
        }                                                                      \
        asm volatile(                                                          \
            "tcgen05.commit.cta_group::1.mbarrier::arrive::one.shared::cluster.b64 [%0];" \
            :: "r"(mb_) : "memory");                                           \
    }                                                                          \
} while (0)

    int t = blockIdx.x;
    int slot = 0;
    if (t < ntiles) {
        STAGE_A(t, A0);
        __syncthreads();
        if (wid == 0) ISSUE_MMA(a0_base, tmem, mbar0);
    }

    while (t < ntiles) {
        const int tn = t + gridDim.x;
        const int nslot = 1 - slot;

        // stage + issue the NEXT tile into the other buffer/D-region
        if (tn < ntiles) {
            STAGE_A(tn, nslot ? A1 : A0);
            __syncthreads();
            if (wid == 0) ISSUE_MMA(nslot ? a1_base : a0_base,
                                    tmem + nslot * 128, nslot ? mbar1 : mbar0);
        }

        // this tile's indices + gather prefetch (half 0 owns e inputs)
        const int i = t * 128 + child;
        const bool live = (i < nc);
        const int p = live ? g_idx[i] : 0;
        float ea[RPE];
        float qpr[32];
        if (half == 0) {
#pragma unroll
            for (int r = 0; r < RPE; r++)
                ea[r] = live ? edge_attr[(size_t)i * RPE + r] : 0.f;
            const float4* qv = (const float4*)&g_qp[(size_t)p * DH];
#pragma unroll
            for (int u = 0; u < 8; u++) {
                float4 v = live ? qv[u] : make_float4(0.f, 0.f, 0.f, 0.f);
                qpr[u * 4 + 0] = v.x; qpr[u * 4 + 1] = v.y;
                qpr[u * 4 + 2] = v.z; qpr[u * 4 + 3] = v.w;
            }
        }

        // wait for THIS tile's MMA
        if (slot) { MBAR_WAIT(mbar1, ph1); ph1 ^= 1; }
        else      { MBAR_WAIT(mbar0, ph0); ph0 ^= 1; }
        asm volatile("tcgen05.fence::after_thread_sync;" ::: "memory");

        const uint32_t dbase = tmem + slot * 128;
        uint32_t dk[32], dv[32];
        if (half == 0) {
            LDTM32(dk, dbase);          // compat D cols 0-31
            LDTM32(dv, dbase + 32);     // v cols 0-31
        } else {
            LDTM32(dv, dbase + 64);     // v cols 32-63
        }
        asm volatile("tcgen05.wait::ld.sync.aligned;" ::: "memory");

        float e4[4];
        if (half == 0 && live) {
#pragma unroll
            for (int h = 0; h < 4; h++) {
                float c = 0.f;
#pragma unroll
                for (int j = 0; j < 8; j++) {
                    int col = h * 8 + j;
                    float kv = __uint_as_float(dk[col]) + bkc[col];
                    float qv = qpr[col] + bqr[col];
#pragma unroll
                    for (int r = 0; r < RPE; r++) {
                        kv += ea[r] * wkr_s[r][col];
                        qv += ea[r] * wqr_s[r][col];
                    }
                    c += qv * kv;
                }
                e4[h] = __expf(c);
            }
            *(float4*)&e_s[child][0] = make_float4(e4[0], e4[1], e4[2], e4[3]);
            asm volatile("red.global.add.v4.f32 [%0], {%1,%2,%3,%4};"
                         :: "l"(g_s + (size_t)p * H),
                            "f"(e4[0]), "f"(e4[1]), "f"(e4[2]), "f"(e4[3]) : "memory");
            // scatter v cols 0-31 (heads 0,1)
            float* dst = out + (size_t)p * DIM;
#pragma unroll
            for (int g = 0; g < 8; g++) {
                int col = g * 4;
                float e = e4[g >> 2];
                float r0 = (__uint_as_float(dv[col + 0]) + bv_s[col + 0]) * e;
                float r1 = (__uint_as_float(dv[col + 1]) + bv_s[col + 1]) * e;
                float r2 = (__uint_as_float(dv[col + 2]) + bv_s[col + 2]) * e;
                float r3 = (__uint_as_float(dv[col + 3]) + bv_s[col + 3]) * e;
                asm volatile("red.global.add.v4.f32 [%0], {%1,%2,%3,%4};"
                             :: "l"(dst + col), "f"(r0), "f"(r1), "f"(r2), "f"(r3)
                             : "memory");
            }
        }
        __syncthreads();   // e_s visible to half 1
        if (half == 1 && live) {
            float ehi0 = e_s[child][2];
            float ehi1 = e_s[child][3];
            float* dst = out + (size_t)p * DIM + 32;
#pragma unroll
            for (int g = 0; g < 8; g++) {
                int col = g * 4;               // 0..28 within upper half
                float e = (g < 4) ? ehi0 : ehi1;
                float r0 = (__uint_as_float(dv[col + 0]) + bv_s[32 + col + 0]) * e;
                float r1 = (__uint_as_float(dv[col + 1]) + bv_s[32 + col + 1]) * e;
                float r2 = (__uint_as_float(dv[col + 2]) + bv_s[32 + col + 2]) * e;
                float r3 = (__uint_as_float(dv[col + 3]) + bv_s[32 + col + 3]) * e;
                asm volatile("red.global.add.v4.f32 [%0], {%1,%2,%3,%4};"
                             :: "l"(dst + col), "f"(r0), "f"(r1), "f"(r2), "f"(r3)
                             : "memory");
            }
        }
        asm volatile("tcgen05.fence::before_thread_sync;" ::: "memory");
        __syncthreads();   // D[slot] consumed; buf[slot] free for restage

        t = tn;
        slot = nslot;
    }

    __syncthreads();
    if (tid == 0) {
        asm volatile("mbarrier.inval.shared.b64 [%0];" :: "r"(mbar0) : "memory");
        asm volatile("mbarrier.inval.shared.b64 [%0];" :: "r"(mbar1) : "memory");
    }
    __syncthreads();
    if (wid == 0)
        asm volatile("tcgen05.dealloc.cta_group::1.sync.aligned.b32 %0, %1;"
                     :: "r"(tmem), "r"(256u));
#else
    // fallback for the plain compute_103 PTX pass (never executes on the GPU)
    const int tid = threadIdx.x;
    for (int tile = blockIdx.x; tile < ntiles; tile += gridDim.x) {
        int i = tile * 128 + (tid & 127);
        if (tid < 128 && i < nc) {
            int p = g_idx[i];
            float ea[RPE];
            for (int r = 0; r < RPE; r++) ea[r] = edge_attr[(size_t)i * RPE + r];
            float e4[4];
            for (int h = 0; h < 4; h++) {
                float c = 0.f;
                for (int j = 0; j < 8; j++) {
                    int col = h * 8 + j;
                    float kv = bkv[col] + bk_rpe[col];
                    for (int cd = 0; cd < 64; cd++)
                        kv += x_child[(size_t)i * DIM + cd] * wkv[cd * KVW + col];
                    float qv = g_qp[(size_t)p * DH + col] + bq_rpe[col];
                    for (int r = 0; r < RPE; r++) {
                        kv += ea[r] * wk_rpe[r * DH + col];
                        qv += ea[r] * wq_rpe[r * DH + col];
                    }
                    c += qv * kv;
                }
                e4[h] = __expf(c);
            }
            for (int h = 0; h < 4; h++) atomicAdd(g_s + (size_t)p * H + h, e4[h]);
            for (int j = 0; j < 64; j++) {
                float a = bkv[DH + j];
                for (int cd = 0; cd < 64; cd++)
                    a += x_child[(size_t)i * DIM + cd] * wkv[cd * KVW + DH + j];
                atomicAdd(out + (size_t)p * DIM + j, a * e4[j >> 4]);
            }
        }
    }
#endif
}

// ---------------- final normalize ----------------
__global__ void norm_kernel(float* __restrict__ out, int np) {
    int idx = blockIdx.x * blockDim.x + threadIdx.x;
    if (idx >= np * 16) return;
    int p = idx >> 4, grp = idx & 15;
    float s = g_s[p * H + (grp >> 2)];
    float inv = 1.0f / (s + 1e-16f);
    float4 v = *(const float4*)&out[(size_t)p * DIM + grp * 4];
    v.x *= inv; v.y *= inv; v.z *= inv; v.w *= inv;
    *(float4*)&out[(size_t)p * DIM + grp * 4] = v;
}

// ---------------- launch ----------------
extern "C" void kernel_launch(void* const* d_in, const int* in_sizes, int n_in,
                              void* d_out, int out_size) {
    const float* x_child   = (const float*)d_in[0];
    const float* x_parent  = (const float*)d_in[1];
    const void*  index     = d_in[2];
    const float* edge_attr = (const float*)d_in[3];
    const float* wq        = (const float*)d_in[4];
    const float* bq        = (const float*)d_in[5];
    const float* wkv       = (const float*)d_in[6];
    const float* bkv       = (const float*)d_in[7];
    const float* wk_rpe    = (const float*)d_in[8];
    const float* bk_rpe    = (const float*)d_in[9];
    const float* wq_rpe    = (const float*)d_in[10];
    const float* bq_rpe    = (const float*)d_in[11];
    float* out = (float*)d_out;

    const int nc = in_sizes[0] / DIM;
    const int np = in_sizes[1] / DIM;

    static int attr_done = 0;
    if (!attr_done) {
        cudaFuncSetAttribute(fused_kernel,
                             cudaFuncAttributeMaxDynamicSharedMemorySize, FDYN_BYTES);
        attr_done = 1;
    }

    cudaMemsetAsync(d_out, 0, (size_t)out_size * sizeof(float));
    void* s_addr = nullptr;
    cudaGetSymbolAddress(&s_addr, g_s);
    cudaMemsetAsync(s_addr, 0, (size_t)np * H * sizeof(float));

    detect_kernel<<<1, 256>>>((const unsigned int*)index, nc);
    cvt_index_kernel<<<(nc + 255) / 256, 256>>>(index, nc);

    qp_kernel<<<208, 256>>>(x_parent, wq, bq, np);

    const int ntiles = (nc + 127) / 128;
    fused_kernel<<<148, 256, FDYN_BYTES>>>(x_child, edge_attr, wkv, bkv,
                                           wk_rpe, bk_rpe, wq_rpe, bq_rpe,
                                           out, nc, ntiles);

    norm_kernel<<<(np * 16 + 255) / 256, 256>>>(out, np);
}

// round 16
// speedup vs baseline: 1.1683x; 1.1226x over previous
#include <cuda_runtime.h>
#include <cuda_bf16.h>
#include <cstdint>

#define NC_MAX 1000000
#define NP_MAX 100000
#define DIM 64
#define H 4
#define DQK 8
#define DH 32
#define RPE 9
#define KVW 96
#define SCALE 0.35355339059327373f  // 8^-0.5

#if defined(__CUDA_ARCH_FEAT_SM103_ALL) || defined(__CUDA_ARCH_FEAT_SM100_ALL)
#define HAS_TCGEN05 1
#else
#define HAS_TCGEN05 0
#endif

// ---------------- smem helpers ----------------
__device__ __forceinline__ uint32_t smem_u32(const void* p) {
    uint32_t a;
    asm("{ .reg .u64 t; cvta.to.shared.u64 t, %1; cvt.u32.u64 %0, t; }"
        : "=r"(a) : "l"(p));
    return a;
}
#define SW128(b) ((b) ^ (((b) >> 3) & 0x70))

#if HAS_TCGEN05
__device__ __forceinline__ uint32_t elect1() {
    uint32_t p;
    asm volatile("{ .reg .pred p; elect.sync _|p, 0xFFFFFFFF; selp.b32 %0, 1, 0, p; }"
                 : "=r"(p));
    return p;
}
__device__ __forceinline__ uint64_t mk_desc(uint32_t addr) {
    return ((uint64_t)2 << 61) | ((uint64_t)1 << 46) | ((uint64_t)64 << 32)
         | ((uint64_t)1 << 16) | ((uint64_t)(addr >> 4) & 0x3FFF);
}
__device__ __forceinline__ float tf32_rna(float x) {
    uint32_t u;
    asm("cvt.rna.tf32.f32 %0, %1;" : "=r"(u) : "f"(x));
    return __uint_as_float(u);
}

#define TCGEN05_MMA_TF32_SS(dt, ad, bd, id, en) do {                           \
    uint32_t _en = (en) ? 1u : 0u;                                             \
    asm volatile("{\n\t.reg .pred p;\n\tsetp.ne.u32 p, %5, 0;\n\t"             \
        "tcgen05.mma.cta_group::1.kind::tf32 [%0], %1, %2, %3, {%4,%4,%4,%4}, p;\n\t}" \
        :: "r"(dt), "l"(ad), "l"(bd), "r"(id), "r"(0u), "r"(_en) : "memory");  \
} while (0)

#define LDTM32(r, addr)                                                        \
    asm volatile("tcgen05.ld.sync.aligned.32x32b.x32.b32 "                     \
        "{%0,%1,%2,%3,%4,%5,%6,%7,%8,%9,%10,%11,%12,%13,%14,%15,"              \
        "%16,%17,%18,%19,%20,%21,%22,%23,%24,%25,%26,%27,%28,%29,%30,%31}, [%32];" \
        : "=r"((r)[0]),"=r"((r)[1]),"=r"((r)[2]),"=r"((r)[3]),                 \
          "=r"((r)[4]),"=r"((r)[5]),"=r"((r)[6]),"=r"((r)[7]),                 \
          "=r"((r)[8]),"=r"((r)[9]),"=r"((r)[10]),"=r"((r)[11]),               \
          "=r"((r)[12]),"=r"((r)[13]),"=r"((r)[14]),"=r"((r)[15]),             \
          "=r"((r)[16]),"=r"((r)[17]),"=r"((r)[18]),"=r"((r)[19]),             \
          "=r"((r)[20]),"=r"((r)[21]),"=r"((r)[22]),"=r"((r)[23]),             \
          "=r"((r)[24]),"=r"((r)[25]),"=r"((r)[26]),"=r"((r)[27]),             \
          "=r"((r)[28]),"=r"((r)[29]),"=r"((r)[30]),"=r"((r)[31]) : "r"(addr))

#define MBAR_WAIT(mbar, ph) do {                                               \
    uint32_t _done;                                                            \
    asm volatile("{\n\t.reg .pred p;\n\t"                                      \
        "mbarrier.try_wait.parity.acquire.cta.shared::cta.b64 p, [%1], %2;\n\t"\
        "selp.b32 %0, 1, 0, p;\n\t}"                                           \
        : "=r"(_done) : "r"(mbar), "r"(ph) : "memory");                        \
    if (!_done) {                                                              \
        asm volatile("{\n\t.reg .pred P1;\n\t"                                 \
            "WL_%=:\n\t"                                                       \
            "mbarrier.try_wait.parity.acquire.cta.shared::cta.b64 P1, [%0], %1, 0x989680;\n\t" \
            "@P1 bra.uni WD_%=;\n\t"                                           \
            "bra.uni WL_%=;\n\t"                                               \
            "WD_%=:\n\t}"                                                      \
            :: "r"(mbar), "r"(ph) : "memory");                                 \
    }                                                                          \
} while (0)

#define IDESC_V ((1u << 4) | (2u << 7) | (2u << 10) | (8u << 17) | (8u << 24))
#define IDESC_C ((1u << 4) | (2u << 7) | (2u << 10) | (4u << 17) | (8u << 24))
#endif  // HAS_TCGEN05

// ---------------- device scratch ----------------
__device__ __align__(16) float g_qp[NP_MAX * DH];
__device__ __align__(16) float g_s[NP_MAX * H];
__device__ int g_idx[NC_MAX];
__device__ int g_is64;

// ---------------- index dtype detection ----------------
__global__ void detect_kernel(const unsigned int* __restrict__ raw, int nc) {
    __shared__ int found;
    if (threadIdx.x == 0) found = 0;
    __syncthreads();
    int limit = nc / 2; if (limit > 2048) limit = 2048;
    for (int i = threadIdx.x; i < limit; i += blockDim.x)
        if (raw[2 * i + 1] != 0u) found = 1;
    __syncthreads();
    if (threadIdx.x == 0) g_is64 = (found == 0) ? 1 : 0;
}

__global__ void cvt_index_kernel(const void* __restrict__ idxp, int nc) {
    int i = blockIdx.x * blockDim.x + threadIdx.x;
    if (i >= nc) return;
    if (g_is64) g_idx[i] = (int)((const long long*)idxp)[i];
    else        g_idx[i] = ((const int*)idxp)[i];
}

// ---------------- parent query projection ----------------
__global__ void __launch_bounds__(256, 2) qp_kernel(
    const float* __restrict__ x_parent, const float* __restrict__ wq,
    const float* __restrict__ bq, int np)
{
    const int t = threadIdx.x & 31;
    const int w = threadIdx.x >> 5;
    __shared__ __align__(16) float xs[8][64];

    float wr[64];
#pragma unroll
    for (int c = 0; c < 64; c++) wr[c] = wq[c * DH + t];
    const float b = bq[t];

    const int warps_total = gridDim.x * 8;
    for (int p = blockIdx.x * 8 + w; p < np; p += warps_total) {
        size_t base = (size_t)p * DIM;
        xs[w][t]      = x_parent[base + t];
        xs[w][t + 32] = x_parent[base + 32 + t];
        __syncwarp();
        float a0 = b, a1 = 0.f, a2 = 0.f, a3 = 0.f;
#pragma unroll
        for (int c = 0; c < 64; c += 4) {
            float4 xv = *(const float4*)&xs[w][c];
            a0 += xv.x * wr[c];
            a1 += xv.y * wr[c + 1];
            a2 += xv.z * wr[c + 2];
            a3 += xv.w * wr[c + 3];
        }
        g_qp[(size_t)p * DH + t] = ((a0 + a1) + (a2 + a3)) * SCALE;
        __syncwarp();
    }
}

// ======================= fused, depth-2 pipelined, 2 CTAs/SM =======================
// Tile M=128 children, 128 threads. Double-buffered Ah ONLY (x hi); the w
// residual Bvl is kept so D_v = xh@wh + xh@wl = xh@w (one-sided tf32 error,
// ~5e-4 total). smem ~105KB -> 2 CTAs/SM: explicit pipeline + cross-CTA overlap.
#define AH_BYTES (128 * 64 * 4)   // 32768 per buffer
#define BK_BYTES (32 * 64 * 4)    // 8192
#define BV_BYTES (64 * 64 * 4)    // 16384
#define FDYN_BYTES (2 * AH_BYTES + BK_BYTES + 2 * BV_BYTES + 1024)  // 107520

__device__ __forceinline__ uint32_t a_off(int child, int col) {
    return SW128((uint32_t)(((child >> 3) + ((col >= 32) ? 16 : 0)) * 1024
                 + (child & 7) * 128 + (col & 31) * 4));
}
__device__ __forceinline__ uint32_t bk_off(int n, int k) {
    return SW128((uint32_t)(((n >> 3) + (k >> 5) * 4) * 1024
                 + (n & 7) * 128 + (k & 31) * 4));
}
__device__ __forceinline__ uint32_t bv_off(int n, int k) {
    return SW128((uint32_t)(((n >> 3) + (k >> 5) * 8) * 1024
                 + (n & 7) * 128 + (k & 31) * 4));
}

__global__ void __launch_bounds__(128) fused_kernel(
    const float* __restrict__ x_child, const float* __restrict__ edge_attr,
    const float* __restrict__ wkv, const float* __restrict__ bkv,
    const float* __restrict__ wk_rpe, const float* __restrict__ bk_rpe,
    const float* __restrict__ wq_rpe, const float* __restrict__ bq_rpe,
    float* __restrict__ out, int nc, int ntiles)
{
#if HAS_TCGEN05
    extern __shared__ __align__(16) char fdyn[];
    __shared__ __align__(16) float wkr_s[RPE][32];
    __shared__ __align__(16) float wqr_s[RPE][32];
    __shared__ __align__(16) float bkc[32];
    __shared__ __align__(16) float bqr[32];
    __shared__ __align__(16) float bv_s[64];
    __shared__ __align__(8) unsigned long long mbar_store[2];
    __shared__ uint32_t tmem_ptr_store;

    const int tid = threadIdx.x;
    const int wid = tid >> 5;

    uint32_t base_u = smem_u32(fdyn);
    uint32_t pad = (1024u - (base_u & 1023u)) & 1023u;
    char* A0  = fdyn + pad;
    char* A1  = A0 + AH_BYTES;
    char* Bk  = A1 + AH_BYTES;
    char* Bvh = Bk + BK_BYTES;
    char* Bvl = Bvh + BV_BYTES;
    const uint32_t a0_base  = base_u + pad;
    const uint32_t a1_base  = a0_base + AH_BYTES;
    const uint32_t bk_base  = a1_base + AH_BYTES;
    const uint32_t bvh_base = bk_base + BK_BYTES;
    const uint32_t bvl_base = bvh_base + BV_BYTES;
    const uint32_t mbar0 = smem_u32(&mbar_store[0]);
    const uint32_t mbar1 = smem_u32(&mbar_store[1]);

    if (wid == 0) {
        asm volatile("tcgen05.alloc.cta_group::1.sync.aligned.shared::cta.b32 [%0], %1;"
                     :: "r"(smem_u32(&tmem_ptr_store)), "r"(256u) : "memory");
        asm volatile("tcgen05.relinquish_alloc_permit.cta_group::1.sync.aligned;");
    }
    if (tid == 0) {
        asm volatile("mbarrier.init.shared.b64 [%0], %1;" :: "r"(mbar0), "r"(1u) : "memory");
        asm volatile("mbarrier.init.shared.b64 [%0], %1;" :: "r"(mbar1), "r"(1u) : "memory");
    }

    // one-time weight staging
    for (int idx = tid; idx < 32 * 64; idx += 128) {
        int n = idx >> 6, k = idx & 63;
        *(float*)(Bk + bk_off(n, k)) = wkv[k * KVW + n];
    }
    for (int idx = tid; idx < 64 * 64; idx += 128) {
        int n = idx >> 6, k = idx & 63;
        float w = wkv[k * KVW + DH + n];
        float hi = tf32_rna(w);
        *(float*)(Bvh + bv_off(n, k)) = hi;
        *(float*)(Bvl + bv_off(n, k)) = w - hi;
    }
    for (int idx = tid; idx < RPE * 32; idx += 128) {
        wkr_s[0][idx] = wk_rpe[idx];
        wqr_s[0][idx] = wq_rpe[idx];
    }
    if (tid < 32) {
        bkc[tid] = bkv[tid] + bk_rpe[tid];
        bqr[tid] = bq_rpe[tid];
    }
    if (tid < 64) bv_s[tid] = bkv[DH + tid];
    __syncthreads();

    const uint32_t tmem = tmem_ptr_store;
    const uint64_t bk_d  = mk_desc(bk_base);
    const uint64_t bvh_d = mk_desc(bvh_base);
    const uint64_t bvl_d = mk_desc(bvl_base);
    uint32_t ph0 = 0, ph1 = 0;

#define STAGE_A(t_, Ah_) do {                                                  \
    const int _i0 = (t_) * 128;                                                \
    _Pragma("unroll")                                                          \
    for (int _k = 0; _k < 16; _k++) {                                          \
        int _idx = tid + 128 * _k;                                             \
        int _ch = _idx >> 4, _c4 = _idx & 15;                                  \
        int _i2 = _i0 + _ch;                                                   \
        float4 _xv = make_float4(0.f, 0.f, 0.f, 0.f);                          \
        if (_i2 < nc) _xv = *(const float4*)&x_child[(size_t)_i2 * DIM + _c4 * 4]; \
        float4 _hi;                                                            \
        _hi.x = tf32_rna(_xv.x); _hi.y = tf32_rna(_xv.y);                      \
        _hi.z = tf32_rna(_xv.z); _hi.w = tf32_rna(_xv.w);                      \
        *(float4*)((Ah_) + a_off(_ch, _c4 * 4)) = _hi;                         \
    }                                                                          \
    asm volatile("fence.proxy.async.shared::cta;" ::: "memory");               \
} while (0)

#define ISSUE_MMA(abase_, dt_, mb_) do {                                       \
    const uint64_t _ah_d = mk_desc(abase_);                                    \
    asm volatile("tcgen05.fence::after_thread_sync;" ::: "memory");            \
    if (elect1()) {                                                            \
        _Pragma("unroll")                                                      \
        for (int _s = 0; _s < 8; _s++) {                                       \
            uint64_t _ao = (uint64_t)((_s >> 2) * 1024 + (_s & 3) * 2);        \
            uint64_t _bo = (uint64_t)((_s >> 2) * 256 + (_s & 3) * 2);         \
            TCGEN05_MMA_TF32_SS((dt_), _ah_d + _ao, bk_d + _bo, IDESC_C, _s > 0); \
        }                                                                      \
        _Pragma("unroll")                                                      \
        for (int _pass = 0; _pass < 2; _pass++) {                              \
            uint64_t _bd = (_pass == 1) ? bvl_d : bvh_d;                       \
            _Pragma("unroll")                                                  \
            for (int _s = 0; _s < 8; _s++) {                                   \
                uint64_t _ao = (uint64_t)((_s >> 2) * 1024 + (_s & 3) * 2);    \
                uint64_t _bo = (uint64_t)((_s >> 2) * 512 + (_s & 3) * 2);     \
                TCGEN05_MMA_TF32_SS((dt_) + 32, _ah_d + _ao, _bd + _bo, IDESC_V, \
                                    !(_pass == 0 && _s == 0));                 \
            }                                                                  \
        }                                                                      \
        asm volatile(                                                          \
            "tcgen05.commit.cta_group::1.mbarrier::arrive::one.shared::cluster.b64 [%0];" \
            :: "r"(mb_) : "memory");                                           \
    }                                                                          \
} while (0)

    int t = blockIdx.x;
    int slot = 0;
    if (t < ntiles) {
        STAGE_A(t, A0);
        __syncthreads();
        if (wid == 0) ISSUE_MMA(a0_base, tmem, mbar0);
    }

    while (t < ntiles) {
        const int tn = t + gridDim.x;
        const int nslot = 1 - slot;

        // stage + issue the NEXT tile into the other buffer/D-region
        if (tn < ntiles) {
            STAGE_A(tn, nslot ? A1 : A0);
            __syncthreads();
            if (wid == 0) ISSUE_MMA(nslot ? a1_base : a0_base,
                                    tmem + nslot * 128, nslot ? mbar1 : mbar0);
        }

        // prefetch this tile's gathers while MMAs are in flight
        const int i = t * 128 + tid;
        const bool live = (i < nc);
        const int p = live ? g_idx[i] : 0;
        float ea[RPE];
#pragma unroll
        for (int r = 0; r < RPE; r++)
            ea[r] = live ? edge_attr[(size_t)i * RPE + r] : 0.f;
        float qpr[32];
        {
            const float4* qv = (const float4*)&g_qp[(size_t)p * DH];
#pragma unroll
            for (int u = 0; u < 8; u++) {
                float4 v = live ? qv[u] : make_float4(0.f, 0.f, 0.f, 0.f);
                qpr[u * 4 + 0] = v.x; qpr[u * 4 + 1] = v.y;
                qpr[u * 4 + 2] = v.z; qpr[u * 4 + 3] = v.w;
            }
        }

        // wait for THIS tile's MMA
        if (slot) { MBAR_WAIT(mbar1, ph1); ph1 ^= 1; }
        else      { MBAR_WAIT(mbar0, ph0); ph0 ^= 1; }
        asm volatile("tcgen05.fence::after_thread_sync;" ::: "memory");

        uint32_t dk[32], dv[64];
        const uint32_t dbase = tmem + slot * 128;
        LDTM32(dk, dbase);
        LDTM32(dv, dbase + 32);
        LDTM32(dv + 32, dbase + 64);
        asm volatile("tcgen05.wait::ld.sync.aligned;" ::: "memory");

        if (live) {
            float e4[4];
#pragma unroll
            for (int h = 0; h < 4; h++) {
                float c = 0.f;
#pragma unroll
                for (int j = 0; j < 8; j++) {
                    int col = h * 8 + j;
                    float kv = __uint_as_float(dk[col]) + bkc[col];
                    float qv = qpr[col] + bqr[col];
#pragma unroll
                    for (int r = 0; r < RPE; r++) {
                        kv += ea[r] * wkr_s[r][col];
                        qv += ea[r] * wqr_s[r][col];
                    }
                    c += qv * kv;
                }
                e4[h] = __expf(c);
            }
            asm volatile("red.global.add.v4.f32 [%0], {%1,%2,%3,%4};"
                         :: "l"(g_s + (size_t)p * H),
                            "f"(e4[0]), "f"(e4[1]), "f"(e4[2]), "f"(e4[3]) : "memory");

            float* dst = out + (size_t)p * DIM;
#pragma unroll
            for (int g = 0; g < 16; g++) {
                int col = g * 4;
                float e = e4[g >> 2];
                float r0 = (__uint_as_float(dv[col + 0]) + bv_s[col + 0]) * e;
                float r1 = (__uint_as_float(dv[col + 1]) + bv_s[col + 1]) * e;
                float r2 = (__uint_as_float(dv[col + 2]) + bv_s[col + 2]) * e;
                float r3 = (__uint_as_float(dv[col + 3]) + bv_s[col + 3]) * e;
                asm volatile("red.global.add.v4.f32 [%0], {%1,%2,%3,%4};"
                             :: "l"(dst + col), "f"(r0), "f"(r1), "f"(r2), "f"(r3)
                             : "memory");
            }
        }
        asm volatile("tcgen05.fence::before_thread_sync;" ::: "memory");
        __syncthreads();   // D[slot] consumed; buf[slot] free for restage

        t = tn;
        slot = nslot;
    }

    __syncthreads();
    if (tid == 0) {
        asm volatile("mbarrier.inval.shared.b64 [%0];" :: "r"(mbar0) : "memory");
        asm volatile("mbarrier.inval.shared.b64 [%0];" :: "r"(mbar1) : "memory");
    }
    __syncthreads();
    if (wid == 0)
        asm volatile("tcgen05.dealloc.cta_group::1.sync.aligned.b32 %0, %1;"
                     :: "r"(tmem), "r"(256u));
#else
    // fallback for the plain compute_103 PTX pass (never executes on the GPU)
    const int tid = threadIdx.x;
    for (int tile = blockIdx.x; tile < ntiles; tile += gridDim.x) {
        int i = tile * 128 + tid;
        if (i < nc) {
            int p = g_idx[i];
            float ea[RPE];
            for (int r = 0; r < RPE; r++) ea[r] = edge_attr[(size_t)i * RPE + r];
            float e4[4];
            for (int h = 0; h < 4; h++) {
                float c = 0.f;
                for (int j = 0; j < 8; j++) {
                    int col = h * 8 + j;
                    float kv = bkv[col] + bk_rpe[col];
                    for (int cd = 0; cd < 64; cd++)
                        kv += x_child[(size_t)i * DIM + cd] * wkv[cd * KVW + col];
                    float qv = g_qp[(size_t)p * DH + col] + bq_rpe[col];
                    for (int r = 0; r < RPE; r++) {
                        kv += ea[r] * wk_rpe[r * DH + col];
                        qv += ea[r] * wq_rpe[r * DH + col];
                    }
                    c += qv * kv;
                }
                e4[h] = __expf(c);
            }
            for (int h = 0; h < 4; h++) atomicAdd(g_s + (size_t)p * H + h, e4[h]);
            for (int j = 0; j < 64; j++) {
                float a = bkv[DH + j];
                for (int cd = 0; cd < 64; cd++)
                    a += x_child[(size_t)i * DIM + cd] * wkv[cd * KVW + DH + j];
                atomicAdd(out + (size_t)p * DIM + j, a * e4[j >> 4]);
            }
        }
    }
#endif
}

// ---------------- final normalize ----------------
__global__ void norm_kernel(float* __restrict__ out, int np) {
    int idx = blockIdx.x * blockDim.x + threadIdx.x;
    if (idx >= np * 16) return;
    int p = idx >> 4, grp = idx & 15;
    float s = g_s[p * H + (grp >> 2)];
    float inv = 1.0f / (s + 1e-16f);
    float4 v = *(const float4*)&out[(size_t)p * DIM + grp * 4];
    v.x *= inv; v.y *= inv; v.z *= inv; v.w *= inv;
    *(float4*)&out[(size_t)p * DIM + grp * 4] = v;
}

// ---------------- launch ----------------
extern "C" void kernel_launch(void* const* d_in, const int* in_sizes, int n_in,
                              void* d_out, int out_size) {
    const float* x_child   = (const float*)d_in[0];
    const float* x_parent  = (const float*)d_in[1];
    const void*  index     = d_in[2];
    const float* edge_attr = (const float*)d_in[3];
    const float* wq        = (const float*)d_in[4];
    const float* bq        = (const float*)d_in[5];
    const float* wkv       = (const float*)d_in[6];
    const float* bkv       = (const float*)d_in[7];
    const float* wk_rpe    = (const float*)d_in[8];
    const float* bk_rpe    = (const float*)d_in[9];
    const float* wq_rpe    = (const float*)d_in[10];
    const float* bq_rpe    = (const float*)d_in[11];
    float* out = (float*)d_out;

    const int nc = in_sizes[0] / DIM;
    const int np = in_sizes[1] / DIM;

    static int attr_done = 0;
    if (!attr_done) {
        cudaFuncSetAttribute(fused_kernel,
                             cudaFuncAttributeMaxDynamicSharedMemorySize, FDYN_BYTES);
        attr_done = 1;
    }

    cudaMemsetAsync(d_out, 0, (size_t)out_size * sizeof(float));
    void* s_addr = nullptr;
    cudaGetSymbolAddress(&s_addr, g_s);
    cudaMemsetAsync(s_addr, 0, (size_t)np * H * sizeof(float));

    detect_kernel<<<1, 256>>>((const unsigned int*)index, nc);
    cvt_index_kernel<<<(nc + 255) / 256, 256>>>(index, nc);

    qp_kernel<<<208, 256>>>(x_parent, wq, bq, np);

    const int ntiles = (nc + 127) / 128;
    fused_kernel<<<296, 128, FDYN_BYTES>>>(x_child, edge_attr, wkv, bkv,
                                           wk_rpe, bk_rpe, wq_rpe, bq_rpe,
                                           out, nc, ntiles);

    norm_kernel<<<(np * 16 + 255) / 256, 256>>>(out, np);
}

// round 17
// speedup vs baseline: 1.2199x; 1.0441x over previous
#include <cuda_runtime.h>
#include <cuda_bf16.h>
#include <cstdint>

#define NC_MAX 1000000
#define NP_MAX 100000
#define DIM 64
#define H 4
#define DQK 8
#define DH 32
#define RPE 9
#define KVW 96
#define SCALE 0.35355339059327373f  // 8^-0.5

#if defined(__CUDA_ARCH_FEAT_SM103_ALL) || defined(__CUDA_ARCH_FEAT_SM100_ALL)
#define HAS_TCGEN05 1
#else
#define HAS_TCGEN05 0
#endif

// ---------------- smem helpers ----------------
__device__ __forceinline__ uint32_t smem_u32(const void* p) {
    uint32_t a;
    asm("{ .reg .u64 t; cvta.to.shared.u64 t, %1; cvt.u32.u64 %0, t; }"
        : "=r"(a) : "l"(p));
    return a;
}
#define SW128(b) ((b) ^ (((b) >> 3) & 0x70))

#if HAS_TCGEN05
__device__ __forceinline__ uint32_t elect1() {
    uint32_t p;
    asm volatile("{ .reg .pred p; elect.sync _|p, 0xFFFFFFFF; selp.b32 %0, 1, 0, p; }"
                 : "=r"(p));
    return p;
}
__device__ __forceinline__ uint64_t mk_desc(uint32_t addr) {
    return ((uint64_t)2 << 61) | ((uint64_t)1 << 46) | ((uint64_t)64 << 32)
         | ((uint64_t)1 << 16) | ((uint64_t)(addr >> 4) & 0x3FFF);
}
__device__ __forceinline__ float tf32_rna(float x) {
    uint32_t u;
    asm("cvt.rna.tf32.f32 %0, %1;" : "=r"(u) : "f"(x));
    return __uint_as_float(u);
}

#define TCGEN05_MMA_TF32_SS(dt, ad, bd, id, en) do {                           \
    uint32_t _en = (en) ? 1u : 0u;                                             \
    asm volatile("{\n\t.reg .pred p;\n\tsetp.ne.u32 p, %5, 0;\n\t"             \
        "tcgen05.mma.cta_group::1.kind::tf32 [%0], %1, %2, %3, {%4,%4,%4,%4}, p;\n\t}" \
        :: "r"(dt), "l"(ad), "l"(bd), "r"(id), "r"(0u), "r"(_en) : "memory");  \
} while (0)

#define LDTM32(r, addr)                                                        \
    asm volatile("tcgen05.ld.sync.aligned.32x32b.x32.b32 "                     \
        "{%0,%1,%2,%3,%4,%5,%6,%7,%8,%9,%10,%11,%12,%13,%14,%15,"              \
        "%16,%17,%18,%19,%20,%21,%22,%23,%24,%25,%26,%27,%28,%29,%30,%31}, [%32];" \
        : "=r"((r)[0]),"=r"((r)[1]),"=r"((r)[2]),"=r"((r)[3]),                 \
          "=r"((r)[4]),"=r"((r)[5]),"=r"((r)[6]),"=r"((r)[7]),                 \
          "=r"((r)[8]),"=r"((r)[9]),"=r"((r)[10]),"=r"((r)[11]),               \
          "=r"((r)[12]),"=r"((r)[13]),"=r"((r)[14]),"=r"((r)[15]),             \
          "=r"((r)[16]),"=r"((r)[17]),"=r"((r)[18]),"=r"((r)[19]),             \
          "=r"((r)[20]),"=r"((r)[21]),"=r"((r)[22]),"=r"((r)[23]),             \
          "=r"((r)[24]),"=r"((r)[25]),"=r"((r)[26]),"=r"((r)[27]),             \
          "=r"((r)[28]),"=r"((r)[29]),"=r"((r)[30]),"=r"((r)[31]) : "r"(addr))

#define MBAR_WAIT(mbar, ph) do {                                               \
    uint32_t _done;                                                            \
    asm volatile("{\n\t.reg .pred p;\n\t"                                      \
        "mbarrier.try_wait.parity.acquire.cta.shared::cta.b64 p, [%1], %2;\n\t"\
        "selp.b32 %0, 1, 0, p;\n\t}"                                           \
        : "=r"(_done) : "r"(mbar), "r"(ph) : "memory");                        \
    if (!_done) {                                                              \
        asm volatile("{\n\t.reg .pred P1;\n\t"                                 \
            "WL_%=:\n\t"                                                       \
            "mbarrier.try_wait.parity.acquire.cta.shared::cta.b64 P1, [%0], %1, 0x989680;\n\t" \
            "@P1 bra.uni WD_%=;\n\t"                                           \
            "bra.uni WL_%=;\n\t"                                               \
            "WD_%=:\n\t}"                                                      \
            :: "r"(mbar), "r"(ph) : "memory");                                 \
    }                                                                          \
} while (0)

#define IDESC_V ((1u << 4) | (2u << 7) | (2u << 10) | (8u << 17) | (8u << 24))
#define IDESC_C ((1u << 4) | (2u << 7) | (2u << 10) | (4u << 17) | (8u << 24))
#endif  // HAS_TCGEN05

// ---------------- device scratch ----------------
__device__ __align__(16) float g_qp[NP_MAX * DH];
__device__ __align__(16) float g_s[NP_MAX * H];
__device__ int g_idx[NC_MAX];
__device__ int g_is64;

// ---------------- index dtype detection ----------------
__global__ void detect_kernel(const unsigned int* __restrict__ raw, int nc) {
    __shared__ int found;
    if (threadIdx.x == 0) found = 0;
    __syncthreads();
    int limit = nc / 2; if (limit > 2048) limit = 2048;
    for (int i = threadIdx.x; i < limit; i += blockDim.x)
        if (raw[2 * i + 1] != 0u) found = 1;
    __syncthreads();
    if (threadIdx.x == 0) g_is64 = (found == 0) ? 1 : 0;
}

__global__ void cvt_index_kernel(const void* __restrict__ idxp, int nc) {
    int i = blockIdx.x * blockDim.x + threadIdx.x;
    if (i >= nc) return;
    if (g_is64) g_idx[i] = (int)((const long long*)idxp)[i];
    else        g_idx[i] = ((const int*)idxp)[i];
}

// ---------------- parent query projection ----------------
__global__ void __launch_bounds__(256, 2) qp_kernel(
    const float* __restrict__ x_parent, const float* __restrict__ wq,
    const float* __restrict__ bq, int np)
{
    const int t = threadIdx.x & 31;
    const int w = threadIdx.x >> 5;
    __shared__ __align__(16) float xs[8][64];

    float wr[64];
#pragma unroll
    for (int c = 0; c < 64; c++) wr[c] = wq[c * DH + t];
    const float b = bq[t];

    const int warps_total = gridDim.x * 8;
    for (int p = blockIdx.x * 8 + w; p < np; p += warps_total) {
        size_t base = (size_t)p * DIM;
        xs[w][t]      = x_parent[base + t];
        xs[w][t + 32] = x_parent[base + 32 + t];
        __syncwarp();
        float a0 = b, a1 = 0.f, a2 = 0.f, a3 = 0.f;
#pragma unroll
        for (int c = 0; c < 64; c += 4) {
            float4 xv = *(const float4*)&xs[w][c];
            a0 += xv.x * wr[c];
            a1 += xv.y * wr[c + 1];
            a2 += xv.z * wr[c + 2];
            a3 += xv.w * wr[c + 3];
        }
        g_qp[(size_t)p * DH + t] = ((a0 + a1) + (a2 + a3)) * SCALE;
        __syncwarp();
    }
}

// ======================= fused, depth-2 pipelined, 2 CTAs/SM =======================
// Round-16 structure + coalesced out-scatter: after the MMA wait, A[slot] is
// dead, so scaled v is bounced through it (swizzled STS), then warps scatter
// cooperatively — lanes 0-15 cover one child's 16 contiguous float4 groups, so
// each red.v4 touches ~2 parent rows (~4 L1 wavefronts) instead of 32.
#define AH_BYTES (128 * 64 * 4)   // 32768 per buffer
#define BK_BYTES (32 * 64 * 4)    // 8192
#define BV_BYTES (64 * 64 * 4)    // 16384
#define FDYN_BYTES (2 * AH_BYTES + BK_BYTES + 2 * BV_BYTES + 1024)  // 107520

__device__ __forceinline__ uint32_t a_off(int child, int col) {
    return SW128((uint32_t)(((child >> 3) + ((col >= 32) ? 16 : 0)) * 1024
                 + (child & 7) * 128 + (col & 31) * 4));
}
__device__ __forceinline__ uint32_t bk_off(int n, int k) {
    return SW128((uint32_t)(((n >> 3) + (k >> 5) * 4) * 1024
                 + (n & 7) * 128 + (k & 31) * 4));
}
__device__ __forceinline__ uint32_t bv_off(int n, int k) {
    return SW128((uint32_t)(((n >> 3) + (k >> 5) * 8) * 1024
                 + (n & 7) * 128 + (k & 31) * 4));
}

__global__ void __launch_bounds__(128) fused_kernel(
    const float* __restrict__ x_child, const float* __restrict__ edge_attr,
    const float* __restrict__ wkv, const float* __restrict__ bkv,
    const float* __restrict__ wk_rpe, const float* __restrict__ bk_rpe,
    const float* __restrict__ wq_rpe, const float* __restrict__ bq_rpe,
    float* __restrict__ out, int nc, int ntiles)
{
#if HAS_TCGEN05
    extern __shared__ __align__(16) char fdyn[];
    __shared__ __align__(16) float wkr_s[RPE][32];
    __shared__ __align__(16) float wqr_s[RPE][32];
    __shared__ __align__(16) float bkc[32];
    __shared__ __align__(16) float bqr[32];
    __shared__ __align__(16) float bv_s[64];
    __shared__ int pidx_s[128];
    __shared__ __align__(8) unsigned long long mbar_store[2];
    __shared__ uint32_t tmem_ptr_store;

    const int tid = threadIdx.x;
    const int wid = tid >> 5;

    uint32_t base_u = smem_u32(fdyn);
    uint32_t pad = (1024u - (base_u & 1023u)) & 1023u;
    char* A0  = fdyn + pad;
    char* A1  = A0 + AH_BYTES;
    char* Bk  = A1 + AH_BYTES;
    char* Bvh = Bk + BK_BYTES;
    char* Bvl = Bvh + BV_BYTES;
    const uint32_t a0_base  = base_u + pad;
    const uint32_t a1_base  = a0_base + AH_BYTES;
    const uint32_t bk_base  = a1_base + AH_BYTES;
    const uint32_t bvh_base = bk_base + BK_BYTES;
    const uint32_t bvl_base = bvh_base + BV_BYTES;
    const uint32_t mbar0 = smem_u32(&mbar_store[0]);
    const uint32_t mbar1 = smem_u32(&mbar_store[1]);

    if (wid == 0) {
        asm volatile("tcgen05.alloc.cta_group::1.sync.aligned.shared::cta.b32 [%0], %1;"
                     :: "r"(smem_u32(&tmem_ptr_store)), "r"(256u) : "memory");
        asm volatile("tcgen05.relinquish_alloc_permit.cta_group::1.sync.aligned;");
    }
    if (tid == 0) {
        asm volatile("mbarrier.init.shared.b64 [%0], %1;" :: "r"(mbar0), "r"(1u) : "memory");
        asm volatile("mbarrier.init.shared.b64 [%0], %1;" :: "r"(mbar1), "r"(1u) : "memory");
    }

    // one-time weight staging
    for (int idx = tid; idx < 32 * 64; idx += 128) {
        int n = idx >> 6, k = idx & 63;
        *(float*)(Bk + bk_off(n, k)) = wkv[k * KVW + n];
    }
    for (int idx = tid; idx < 64 * 64; idx += 128) {
        int n = idx >> 6, k = idx & 63;
        float w = wkv[k * KVW + DH + n];
        float hi = tf32_rna(w);
        *(float*)(Bvh + bv_off(n, k)) = hi;
        *(float*)(Bvl + bv_off(n, k)) = w - hi;
    }
    for (int idx = tid; idx < RPE * 32; idx += 128) {
        wkr_s[0][idx] = wk_rpe[idx];
        wqr_s[0][idx] = wq_rpe[idx];
    }
    if (tid < 32) {
        bkc[tid] = bkv[tid] + bk_rpe[tid];
        bqr[tid] = bq_rpe[tid];
    }
    if (tid < 64) bv_s[tid] = bkv[DH + tid];
    __syncthreads();

    const uint32_t tmem = tmem_ptr_store;
    const uint64_t bk_d  = mk_desc(bk_base);
    const uint64_t bvh_d = mk_desc(bvh_base);
    const uint64_t bvl_d = mk_desc(bvl_base);
    uint32_t ph0 = 0, ph1 = 0;

#define STAGE_A(t_, Ah_) do {                                                  \
    const int _i0 = (t_) * 128;                                                \
    _Pragma("unroll")                                                          \
    for (int _k = 0; _k < 16; _k++) {                                          \
        int _idx = tid + 128 * _k;                                             \
        int _ch = _idx >> 4, _c4 = _idx & 15;                                  \
        int _i2 = _i0 + _ch;                                                   \
        float4 _xv = make_float4(0.f, 0.f, 0.f, 0.f);                          \
        if (_i2 < nc) _xv = *(const float4*)&x_child[(size_t)_i2 * DIM + _c4 * 4]; \
        float4 _hi;                                                            \
        _hi.x = tf32_rna(_xv.x); _hi.y = tf32_rna(_xv.y);                      \
        _hi.z = tf32_rna(_xv.z); _hi.w = tf32_rna(_xv.w);                      \
        *(float4*)((Ah_) + a_off(_ch, _c4 * 4)) = _hi;                         \
    }                                                                          \
    asm volatile("fence.proxy.async.shared::cta;" ::: "memory");               \
} while (0)

#define ISSUE_MMA(abase_, dt_, mb_) do {                                       \
    const uint64_t _ah_d = mk_desc(abase_);                                    \
    asm volatile("tcgen05.fence::after_thread_sync;" ::: "memory");            \
    if (elect1()) {                                                            \
        _Pragma("unroll")                                                      \
        for (int _s = 0; _s < 8; _s++) {                                       \
            uint64_t _ao = (uint64_t)((_s >> 2) * 1024 + (_s & 3) * 2);        \
            uint64_t _bo = (uint64_t)((_s >> 2) * 256 + (_s & 3) * 2);         \
            TCGEN05_MMA_TF32_SS((dt_), _ah_d + _ao, bk_d + _bo, IDESC_C, _s > 0); \
        }                                                                      \
        _Pragma("unroll")                                                      \
        for (int _pass = 0; _pass < 2; _pass++) {                              \
            uint64_t _bd = (_pass == 1) ? bvl_d : bvh_d;                       \
            _Pragma("unroll")                                                  \
            for (int _s = 0; _s < 8; _s++) {                                   \
                uint64_t _ao = (uint64_t)((_s >> 2) * 1024 + (_s & 3) * 2);    \
                uint64_t _bo = (uint64_t)((_s >> 2) * 512 + (_s & 3) * 2);     \
                TCGEN05_MMA_TF32_SS((dt_) + 32, _ah_d + _ao, _bd + _bo, IDESC_V, \
                                    !(_pass == 0 && _s == 0));                 \
            }                                                                  \
        }                                                                      \
        asm volatile(                                                          \
            "tcgen05.commit.cta_group::1.mbarrier::arrive::one.shared::cluster.b64 [%0];" \
            :: "r"(mb_) : "memory");                                           \
    }                                                                          \
} while (0)

    int t = blockIdx.x;
    int slot = 0;
    if (t < ntiles) {
        STAGE_A(t, A0);
        __syncthreads();
        if (wid == 0) ISSUE_MMA(a0_base, tmem, mbar0);
    }

    while (t < ntiles) {
        const int tn = t + gridDim.x;
        const int nslot = 1 - slot;

        // stage + issue the NEXT tile into the other buffer/D-region
        if (tn < ntiles) {
            STAGE_A(tn, nslot ? A1 : A0);
            __syncthreads();
            if (wid == 0) ISSUE_MMA(nslot ? a1_base : a0_base,
                                    tmem + nslot * 128, nslot ? mbar1 : mbar0);
        }

        // prefetch this tile's gathers while MMAs are in flight
        const int i = t * 128 + tid;
        const bool live = (i < nc);
        const int p = live ? g_idx[i] : 0;
        pidx_s[tid] = live ? p : -1;
        float ea[RPE];
#pragma unroll
        for (int r = 0; r < RPE; r++)
            ea[r] = live ? edge_attr[(size_t)i * RPE + r] : 0.f;
        float qpr[32];
        {
            const float4* qv = (const float4*)&g_qp[(size_t)p * DH];
#pragma unroll
            for (int u = 0; u < 8; u++) {
                float4 v = live ? qv[u] : make_float4(0.f, 0.f, 0.f, 0.f);
                qpr[u * 4 + 0] = v.x; qpr[u * 4 + 1] = v.y;
                qpr[u * 4 + 2] = v.z; qpr[u * 4 + 3] = v.w;
            }
        }

        // wait for THIS tile's MMA
        if (slot) { MBAR_WAIT(mbar1, ph1); ph1 ^= 1; }
        else      { MBAR_WAIT(mbar0, ph0); ph0 ^= 1; }
        asm volatile("tcgen05.fence::after_thread_sync;" ::: "memory");

        uint32_t dk[32], dv[64];
        const uint32_t dbase = tmem + slot * 128;
        LDTM32(dk, dbase);
        LDTM32(dv, dbase + 32);
        LDTM32(dv + 32, dbase + 64);
        asm volatile("tcgen05.wait::ld.sync.aligned;" ::: "memory");

        char* Acur = slot ? A1 : A0;   // this slot's A is dead: reuse as v bounce
        if (live) {
            float e4[4];
#pragma unroll
            for (int h = 0; h < 4; h++) {
                float c = 0.f;
#pragma unroll
                for (int j = 0; j < 8; j++) {
                    int col = h * 8 + j;
                    float kv = __uint_as_float(dk[col]) + bkc[col];
                    float qv = qpr[col] + bqr[col];
#pragma unroll
                    for (int r = 0; r < RPE; r++) {
                        kv += ea[r] * wkr_s[r][col];
                        qv += ea[r] * wqr_s[r][col];
                    }
                    c += qv * kv;
                }
                e4[h] = __expf(c);
            }
            asm volatile("red.global.add.v4.f32 [%0], {%1,%2,%3,%4};"
                         :: "l"(g_s + (size_t)p * H),
                            "f"(e4[0]), "f"(e4[1]), "f"(e4[2]), "f"(e4[3]) : "memory");

            // bounce scaled v into A[slot] (swizzled, smem pipe)
#pragma unroll
            for (int g = 0; g < 16; g++) {
                int col = g * 4;
                float e = e4[g >> 2];
                float4 st;
                st.x = (__uint_as_float(dv[col + 0]) + bv_s[col + 0]) * e;
                st.y = (__uint_as_float(dv[col + 1]) + bv_s[col + 1]) * e;
                st.z = (__uint_as_float(dv[col + 2]) + bv_s[col + 2]) * e;
                st.w = (__uint_as_float(dv[col + 3]) + bv_s[col + 3]) * e;
                *(float4*)(Acur + a_off(tid, col)) = st;
            }
        }
        __syncthreads();   // v bounce + pidx_s visible

        // cooperative scatter: lanes 0-15 cover one child's 16 groups
#pragma unroll
        for (int k = 0; k < 16; k++) {
            int idx = tid + 128 * k;
            int child = idx >> 4, grp = idx & 15;
            int pp = pidx_s[child];
            if (pp >= 0) {
                float4 r = *(const float4*)(Acur + a_off(child, grp * 4));
                asm volatile("red.global.add.v4.f32 [%0], {%1,%2,%3,%4};"
                             :: "l"(out + (size_t)pp * DIM + grp * 4),
                                "f"(r.x), "f"(r.y), "f"(r.z), "f"(r.w) : "memory");
            }
        }
        asm volatile("tcgen05.fence::before_thread_sync;" ::: "memory");
        __syncthreads();   // A[slot] consumed; free for restage at t+2

        t = tn;
        slot = nslot;
    }

    __syncthreads();
    if (tid == 0) {
        asm volatile("mbarrier.inval.shared.b64 [%0];" :: "r"(mbar0) : "memory");
        asm volatile("mbarrier.inval.shared.b64 [%0];" :: "r"(mbar1) : "memory");
    }
    __syncthreads();
    if (wid == 0)
        asm volatile("tcgen05.dealloc.cta_group::1.sync.aligned.b32 %0, %1;"
                     :: "r"(tmem), "r"(256u));
#else
    // fallback for the plain compute_103 PTX pass (never executes on the GPU)
    const int tid = threadIdx.x;
    for (int tile = blockIdx.x; tile < ntiles; tile += gridDim.x) {
        int i = tile * 128 + tid;
        if (i < nc) {
            int p = g_idx[i];
            float ea[RPE];
            for (int r = 0; r < RPE; r++) ea[r] = edge_attr[(size_t)i * RPE + r];
            float e4[4];
            for (int h = 0; h < 4; h++) {
                float c = 0.f;
                for (int j = 0; j < 8; j++) {
                    int col = h * 8 + j;
                    float kv = bkv[col] + bk_rpe[col];
                    for (int cd = 0; cd < 64; cd++)
                        kv += x_child[(size_t)i * DIM + cd] * wkv[cd * KVW + col];
                    float qv = g_qp[(size_t)p * DH + col] + bq_rpe[col];
                    for (int r = 0; r < RPE; r++) {
                        kv += ea[r] * wk_rpe[r * DH + col];
                        qv += ea[r] * wq_rpe[r * DH + col];
                    }
                    c += qv * kv;
                }
                e4[h] = __expf(c);
            }
            for (int h = 0; h < 4; h++) atomicAdd(g_s + (size_t)p * H + h, e4[h]);
            for (int j = 0; j < 64; j++) {
                float a = bkv[DH + j];
                for (int cd = 0; cd < 64; cd++)
                    a += x_child[(size_t)i * DIM + cd] * wkv[cd * KVW + DH + j];
                atomicAdd(out + (size_t)p * DIM + j, a * e4[j >> 4]);
            }
        }
    }
#endif
}

// ---------------- final normalize ----------------
__global__ void norm_kernel(float* __restrict__ out, int np) {
    int idx = blockIdx.x * blockDim.x + threadIdx.x;
    if (idx >= np * 16) return;
    int p = idx >> 4, grp = idx & 15;
    float s = g_s[p * H + (grp >> 2)];
    float inv = 1.0f / (s + 1e-16f);
    float4 v = *(const float4*)&out[(size_t)p * DIM + grp * 4];
    v.x *= inv; v.y *= inv; v.z *= inv; v.w *= inv;
    *(float4*)&out[(size_t)p * DIM + grp * 4] = v;
}

// ---------------- launch ----------------
extern "C" void kernel_launch(void* const* d_in, const int* in_sizes, int n_in,
                              void* d_out, int out_size) {
    const float* x_child   = (const float*)d_in[0];
    const float* x_parent  = (const float*)d_in[1];
    const void*  index     = d_in[2];
    const float* edge_attr = (const float*)d_in[3];
    const float* wq        = (const float*)d_in[4];
    const float* bq        = (const float*)d_in[5];
    const float* wkv       = (const float*)d_in[6];
    const float* bkv       = (const float*)d_in[7];
    const float* wk_rpe    = (const float*)d_in[8];
    const float* bk_rpe    = (const float*)d_in[9];
    const float* wq_rpe    = (const float*)d_in[10];
    const float* bq_rpe    = (const float*)d_in[11];
    float* out = (float*)d_out;

    const int nc = in_sizes[0] / DIM;
    const int np = in_sizes[1] / DIM;

    static int attr_done = 0;
    if (!attr_done) {
        cudaFuncSetAttribute(fused_kernel,
                             cudaFuncAttributeMaxDynamicSharedMemorySize, FDYN_BYTES);
        attr_done = 1;
    }

    cudaMemsetAsync(d_out, 0, (size_t)out_size * sizeof(float));
    void* s_addr = nullptr;
    cudaGetSymbolAddress(&s_addr, g_s);
    cudaMemsetAsync(s_addr, 0, (size_t)np * H * sizeof(float));

    detect_kernel<<<1, 256>>>((const unsigned int*)index, nc);
    cvt_index_kernel<<<(nc + 255) / 256, 256>>>(index, nc);

    qp_kernel<<<208, 256>>>(x_parent, wq, bq, np);

    const int ntiles = (nc + 127) / 128;
    fused_kernel<<<296, 128, FDYN_BYTES>>>(x_child, edge_attr, wkv, bkv,
                                           wk_rpe, bk_rpe, wq_rpe, bq_rpe,
                                           out, nc, ntiles);

    norm_kernel<<<(np * 16 + 255) / 256, 256>>>(out, np);
}